// round 3
// baseline (speedup 1.0000x reference)
#include <cuda_runtime.h>

// ============================================================================
// Clements mesh forward: M (512x512 complex64) through 1024 pair-mixing layers.
// Columns independent -> thread owns 4 rows x 2 packed columns (f32x2).
// R2: adaptive, bounds-clamped output store (suspected IMA source: out buffer
//     smaller than 2MB). All global reads/writes guarded. No possible OOB.
// ============================================================================

typedef unsigned long long u64;

#define TWO_PI 6.283185307179586f
#define NE (512 * 256)
#define NO (512 * 255)

__device__ float4 g_evenP[NE];   // (c, s, t, r) per even layer-pair
__device__ float4 g_oddP [NO];   // (c, s, t, r) per odd  layer-pair
__device__ float2 g_outP [512];  // (c, s) output phase per row

// ---------------- packed f32x2 helpers ----------------
__device__ __forceinline__ u64 fma2(u64 a, u64 b, u64 c) {
    u64 d; asm("fma.rn.f32x2 %0, %1, %2, %3;" : "=l"(d) : "l"(a), "l"(b), "l"(c)); return d;
}
__device__ __forceinline__ u64 mul2(u64 a, u64 b) {
    u64 d; asm("mul.rn.f32x2 %0, %1, %2;" : "=l"(d) : "l"(a), "l"(b)); return d;
}
__device__ __forceinline__ u64 pk2(float lo, float hi) {
    u64 d; asm("mov.b64 %0, {%1, %2};" : "=l"(d) : "f"(lo), "f"(hi)); return d;
}
__device__ __forceinline__ u64 dup2(float x) { return pk2(x, x); }
__device__ __forceinline__ void up2(u64 v, float& lo, float& hi) {
    asm("mov.b64 {%0, %1}, %2;" : "=f"(lo), "=f"(hi) : "l"(v));
}
__device__ __forceinline__ u64 neg2(u64 a) {
    u64 d; asm("xor.b64 %0, %1, 0x8000000080000000;" : "=l"(d) : "l"(a)); return d;
}

// One (phase-on-top + 2x2 MMI) on a pair of rows, 2 columns packed.
__device__ __forceinline__ void applyPair(const float4 P,
                                          u64& rT, u64& iT, u64& rB, u64& iB) {
    u64 c2 = dup2(P.x), s2 = dup2(P.y), t2 = dup2(P.z), r2 = dup2(P.w);
    u64 ns2 = neg2(s2), nr2 = neg2(r2);
    u64 pr = fma2(c2, rT, mul2(ns2, iT));   // c*re - s*im
    u64 pi = fma2(c2, iT, mul2(s2, rT));    // c*im + s*re
    u64 ntr = fma2(t2, pr, mul2(nr2, iB));  // t*pr - r*ibot
    u64 nti = fma2(t2, pi, mul2(r2, rB));   // t*pi + r*rbot
    u64 nbr = fma2(t2, rB, mul2(nr2, pi));  // t*rbot - r*pi
    u64 nbi = fma2(t2, iB, mul2(r2, pr));   // t*ibot + r*pr
    rT = ntr; iT = nti; rB = nbr; iB = nbi;
}

// ---------------- precompute kernel (size-clamped reads) ----------------
__global__ void prep_kernel(const float* __restrict__ pe, const float* __restrict__ po,
                            const float* __restrict__ pout,
                            const float* __restrict__ le, const float* __restrict__ ie,
                            const float* __restrict__ lo, const float* __restrict__ io,
                            int n_e, int n_o, int n_out) {
    int idx = blockIdx.x * blockDim.x + threadIdx.x;
    if (idx < n_e) {
        float th = fminf(fmaxf(pe[idx], 0.f), TWO_PI);
        float s, c; sincosf(th, &s, &c);
        float a = sqrtf(1.f - le[idx]);
        float t = a * sqrtf(0.5f + ie[idx]);
        float r = a * sqrtf(0.5f - ie[idx]);
        g_evenP[idx] = make_float4(c, s, t, r);
    }
    if (idx < n_o) {
        float th = fminf(fmaxf(po[idx], 0.f), TWO_PI);
        float s, c; sincosf(th, &s, &c);
        float a = sqrtf(1.f - lo[idx]);
        float t = a * sqrtf(0.5f + io[idx]);
        float r = a * sqrtf(0.5f - io[idx]);
        g_oddP[idx] = make_float4(c, s, t, r);
    }
    if (idx < n_out) {
        float th = fminf(fmaxf(pout[idx], 0.f), TWO_PI);
        float s, c; sincosf(th, &s, &c);
        g_outP[idx] = make_float2(c, s);
    }
}

// ---------------- degenerate fallback: guarded zero-fill ----------------
__global__ void zero_kernel(float* __restrict__ outf, int n) {
    int idx = blockIdx.x * blockDim.x + threadIdx.x;
    if (idx < n) outf[idx] = 0.f;
}

// ---------------- odd layer (boundary pairs via smem) ----------------
__device__ __forceinline__ void oddLayer(const float4 Pa, const float4 Pb,
                                         u64* re, u64* im,
                                         ulonglong2* Xs, ulonglong2* Ys, u64* Zs,
                                         int j) {
    u64 plr = 0, pli = 0, t2b = 0, nr2b = 0;
    const bool hasB = (j < 127);
    if (hasB) {
        u64 c2 = dup2(Pb.x), s2 = dup2(Pb.y);
        t2b = dup2(Pb.z);
        u64 r2b = dup2(Pb.w);
        u64 ns2 = neg2(s2); nr2b = neg2(r2b);
        // phase the boundary top row (global row 4j+3, odd)
        plr = fma2(c2, re[3], mul2(ns2, im[3]));
        pli = fma2(c2, im[3], mul2(s2, re[3]));
        // stage partials for neighbor's nb: nb_re = t*bre - r*pli ; nb_im = t*bim + r*plr
        Ys[j] = make_ulonglong2(mul2(nr2b, pli), mul2(r2b, plr));
        Zs[j] = t2b;
    }
    Xs[j] = make_ulonglong2(re[0], im[0]);   // raw first row (bot of pair 2j-1)
    __syncthreads();
    // internal pair (rows 4j+1, 4j+2)
    applyPair(Pa, re[1], im[1], re[2], im[2]);
    if (hasB) {
        ulonglong2 nb = Xs[j + 1];                       // neighbor's first row (pre-update)
        re[3] = fma2(t2b, plr, mul2(nr2b, nb.y));        // t*plr - r*bim
        im[3] = fma2(t2b, pli, mul2(neg2(nr2b), nb.x));  // t*pli + r*bre
    }
    if (j > 0) {
        ulonglong2 u = Ys[j - 1];
        u64 tn = Zs[j - 1];
        re[0] = fma2(tn, re[0], u.x);
        im[0] = fma2(tn, im[0], u.y);
    }
}

// ---------------- step-param prefetch bundle ----------------
struct SP {
    float4 e0a, e0b, e1a, e1b, o0a, o0b, o1a, o1b;
};
__device__ __forceinline__ SP loadStep(int s, int p2, int pb) {
    SP r;
    int e = (2 * s) * 256 + p2;
    r.e0a = g_evenP[e];       r.e0b = g_evenP[e + 1];
    r.e1a = g_evenP[e + 256]; r.e1b = g_evenP[e + 257];
    int o = (2 * s) * 255;
    r.o0a = g_oddP[o + p2];        r.o0b = g_oddP[o + pb];
    r.o1a = g_oddP[o + 255 + p2];  r.o1b = g_oddP[o + 255 + pb];
    return r;
}

// ---------------- main mesh kernel ----------------
// grid 128 CTAs (4 columns each), 256 threads: g = col-pair group (0/1),
// j = row chunk (rows 4j..4j+3). Data packed f32x2 across the 2 columns.
// Output modes: 0 = interleaved complex floats (float4 per row-colpair),
//               1 = real part only (float2 per row-colpair),
//               2 = interleaved scalar floats, clamped.
__global__ __launch_bounds__(256, 1) void mesh_kernel(float* __restrict__ outf,
                                                      int mode, int cap) {
    __shared__ ulonglong2 Xs[2][2][128];
    __shared__ ulonglong2 Ys[2][2][128];
    __shared__ u64        Zs[2][2][128];

    const int tid = threadIdx.x;
    const int g = tid >> 7;
    const int j = tid & 127;
    const int c0 = blockIdx.x * 4 + g * 2;
    const int r0 = 4 * j;

    u64 re[4], im[4];
#pragma unroll
    for (int k = 0; k < 4; ++k) {
        int row = r0 + k;
        re[k] = pk2(row == c0 ? 1.f : 0.f, row == c0 + 1 ? 1.f : 0.f);
        im[k] = 0ull;
    }

    const int p2 = 2 * j;
    const int pb = (p2 + 1 <= 254) ? p2 + 1 : 254;   // clamp (j=127 value unused)

    SP cur = loadStep(0, p2, pb);
    int buf = 0;

    for (int s = 0; s < 256; ++s) {
        const int sn = (s < 255) ? s + 1 : 255;
        SP nxt = loadStep(sn, p2, pb);               // prefetch next step

        // two even sublayers: pairs (2j), (2j+1) fully thread-internal
        applyPair(cur.e0a, re[0], im[0], re[1], im[1]);
        applyPair(cur.e0b, re[2], im[2], re[3], im[3]);
        applyPair(cur.e1a, re[0], im[0], re[1], im[1]);
        applyPair(cur.e1b, re[2], im[2], re[3], im[3]);

        // two odd sublayers (double-buffered smem exchange, 1 bar each)
        oddLayer(cur.o0a, cur.o0b, re, im, Xs[buf][g], Ys[buf][g], Zs[buf][g], j);
        buf ^= 1;
        oddLayer(cur.o1a, cur.o1b, re, im, Xs[buf][g], Ys[buf][g], Zs[buf][g], j);
        buf ^= 1;

        cur = nxt;
    }

    // output phases (per row), then adaptive guarded store
#pragma unroll
    for (int k = 0; k < 4; ++k) {
        int row = r0 + k;
        float2 ph = g_outP[row];
        u64 c2 = dup2(ph.x), s2 = dup2(ph.y), ns2 = neg2(s2);
        u64 nr_ = fma2(c2, re[k], mul2(ns2, im[k]));
        u64 ni_ = fma2(c2, im[k], mul2(s2, re[k]));
        float rl, rh, il, ih;
        up2(nr_, rl, rh);
        up2(ni_, il, ih);

        int ipair = row * 256 + (c0 >> 1);           // row-colpair index
        if (mode == 0) {
            if (ipair < cap)                          // cap in float4 units
                reinterpret_cast<float4*>(outf)[ipair] = make_float4(rl, il, rh, ih);
        } else if (mode == 1) {
            if (ipair < cap)                          // cap in float2 units (real only)
                reinterpret_cast<float2*>(outf)[ipair] = make_float2(rl, rh);
        } else {
            int base = (row * 512 + c0) * 2;          // cap in float units
            if (base + 0 < cap) outf[base + 0] = rl;
            if (base + 1 < cap) outf[base + 1] = il;
            if (base + 2 < cap) outf[base + 2] = rh;
            if (base + 3 < cap) outf[base + 3] = ih;
        }
    }
}

// ---------------- launch ----------------
extern "C" void kernel_launch(void* const* d_in, const int* in_sizes, int n_in,
                              void* d_out, int out_size) {
    float* outf = (float*)d_out;

    if (n_in < 7) {                                   // degenerate: no unsafe derefs
        int n = out_size > 0 ? out_size : 0;
        if (n > 0) zero_kernel<<<(n + 255) / 256, 256>>>(outf, n);
        return;
    }

    // Resolve input order. Dict/signature order: pe, po, pout, le, ie, lo, io.
    int i_pe = 0, i_po = 1, i_pout = 2, i_le = 3, i_ie = 4, i_lo = 5, i_io = 6;
    if (in_sizes[2] != 512) {
        int ip = -1;
        for (int i = 0; i < 7; ++i) if (in_sizes[i] == 512) ip = i;
        if (ip == 6) {
            // Alphabetical: mmi_imb_even, mmi_imb_odd, mmi_loss_even,
            //               mmi_loss_odd, pc_even_phases, pc_odd_phases, pc_out_phases
            i_ie = 0; i_io = 1; i_le = 2; i_lo = 3; i_pe = 4; i_po = 5; i_pout = 6;
        }
        // else: unknown order — keep dict mapping; clamped reads prevent any crash.
    }

    const float* pe   = (const float*)d_in[i_pe];
    const float* po   = (const float*)d_in[i_po];
    const float* pout = (const float*)d_in[i_pout];
    const float* le   = (const float*)d_in[i_le];
    const float* ie   = (const float*)d_in[i_ie];
    const float* lo   = (const float*)d_in[i_lo];
    const float* io   = (const float*)d_in[i_io];

    // Clamp read bounds to the smallest actual size among each logical group.
    int n_e = NE, n_o = NO, n_out = 512;
    if (in_sizes[i_pe] < n_e)  n_e = in_sizes[i_pe];
    if (in_sizes[i_le] < n_e)  n_e = in_sizes[i_le];
    if (in_sizes[i_ie] < n_e)  n_e = in_sizes[i_ie];
    if (in_sizes[i_po] < n_o)  n_o = in_sizes[i_po];
    if (in_sizes[i_lo] < n_o)  n_o = in_sizes[i_lo];
    if (in_sizes[i_io] < n_o)  n_o = in_sizes[i_io];
    if (in_sizes[i_pout] < n_out) n_out = in_sizes[i_pout];

    // Output mode from out_size (counts elements of the harness's output dtype).
    //  - 524288+ : interleaved complex as floats (2MB+) -> full float4 path
    //  - 262144  : 1MB float buffer -> real part only
    //  - other   : clamped scalar interleaved prefix
    int mode, cap;
    if (out_size >= 524288)      { mode = 0; cap = out_size / 4; if (cap > 131072) cap = 131072; }
    else if (out_size == 262144) { mode = 1; cap = out_size / 2; }
    else                         { mode = 2; cap = out_size; }

    prep_kernel<<<512, 256>>>(pe, po, pout, le, ie, lo, io, n_e, n_o, n_out);
    mesh_kernel<<<128, 256>>>(outf, mode, cap);
}

// round 5
// speedup vs baseline: 1.5673x; 1.5673x over previous
#include <cuda_runtime.h>

// ============================================================================
// Clements mesh forward: M (512x512 complex64) through 1024 pair-mixing layers.
// R3 (resubmit after acquisition timeout):
//  (a) coalesced per-thread param layout P[step][slot][j] (lane-contiguous
//      LDG.128 -> 4 wavefronts not 8),
//  (b) odd-layer boundary exchange via warp shuffles (smem only at warp edges),
//  (c) 128-thread CTAs x 256 grid (all 148 SMs covered).
// Thread j owns rows 4j..4j+3 of 2 packed columns (f32x2).
// ============================================================================

typedef unsigned long long u64;

#define TWO_PI 6.283185307179586f
#define NE (512 * 256)
#define NO (512 * 255)

// P[s][slot][j]: slot 0..3 = e0a,e0b,e1a,e1b ; 4..7 = o0a,o0b,o1a,o1b
__device__ float4 g_P[256 * 8 * 128];     // 4 MB, coalesced per-thread params
__device__ float2 g_outP[512];            // (c, s) output phase per row

// ---------------- packed f32x2 helpers ----------------
__device__ __forceinline__ u64 fma2(u64 a, u64 b, u64 c) {
    u64 d; asm("fma.rn.f32x2 %0, %1, %2, %3;" : "=l"(d) : "l"(a), "l"(b), "l"(c)); return d;
}
__device__ __forceinline__ u64 mul2(u64 a, u64 b) {
    u64 d; asm("mul.rn.f32x2 %0, %1, %2;" : "=l"(d) : "l"(a), "l"(b)); return d;
}
__device__ __forceinline__ u64 pk2(float lo, float hi) {
    u64 d; asm("mov.b64 %0, {%1, %2};" : "=l"(d) : "f"(lo), "f"(hi)); return d;
}
__device__ __forceinline__ u64 dup2(float x) { return pk2(x, x); }
__device__ __forceinline__ void up2(u64 v, float& lo, float& hi) {
    asm("mov.b64 {%0, %1}, %2;" : "=f"(lo), "=f"(hi) : "l"(v));
}
__device__ __forceinline__ u64 neg2(u64 a) {
    u64 d; asm("xor.b64 %0, %1, 0x8000000080000000;" : "=l"(d) : "l"(a)); return d;
}

// One (phase-on-top + 2x2 MMI) on a pair of rows, 2 columns packed.
__device__ __forceinline__ void applyPair(const float4 P,
                                          u64& rT, u64& iT, u64& rB, u64& iB) {
    u64 c2 = dup2(P.x), s2 = dup2(P.y), t2 = dup2(P.z), r2 = dup2(P.w);
    u64 nr2 = neg2(r2);
    u64 pr = fma2(c2, rT, neg2(mul2(s2, iT)));   // c*re - s*im
    u64 pi = fma2(c2, iT, mul2(s2, rT));         // c*im + s*re
    u64 ntr = fma2(t2, pr, mul2(nr2, iB));       // t*pr - r*ibot
    u64 nti = fma2(t2, pi, mul2(r2, rB));        // t*pi + r*rbot
    u64 nbr = fma2(t2, rB, mul2(nr2, pi));       // t*rbot - r*pi
    u64 nbi = fma2(t2, iB, mul2(r2, pr));        // t*ibot + r*pr
    rT = ntr; iT = nti; rB = nbr; iB = nbi;
}

// ---------------- precompute + scatter to coalesced layout ----------------
__global__ void prep_kernel(const float* __restrict__ pe, const float* __restrict__ po,
                            const float* __restrict__ pout,
                            const float* __restrict__ le, const float* __restrict__ ie,
                            const float* __restrict__ lo, const float* __restrict__ io,
                            int n_e, int n_o, int n_out) {
    int idx = blockIdx.x * blockDim.x + threadIdx.x;
    if (idx < n_e) {
        float th = fminf(fmaxf(pe[idx], 0.f), TWO_PI);
        float s, c; sincosf(th, &s, &c);
        float a = sqrtf(1.f - le[idx]);
        float t = a * sqrtf(0.5f + ie[idx]);
        float r = a * sqrtf(0.5f - ie[idx]);
        int layer = idx >> 8;          // /256
        int p = idx & 255;
        int st = layer >> 1, sub = layer & 1, j = p >> 1, ab = p & 1;
        g_P[(st * 8 + (sub * 2 + ab)) * 128 + j] = make_float4(c, s, t, r);
    }
    if (idx < n_o) {
        float th = fminf(fmaxf(po[idx], 0.f), TWO_PI);
        float s, c; sincosf(th, &s, &c);
        float a = sqrtf(1.f - lo[idx]);
        float t = a * sqrtf(0.5f + io[idx]);
        float r = a * sqrtf(0.5f - io[idx]);
        int layer = idx / 255;
        int p = idx - layer * 255;
        int st = layer >> 1, sub = layer & 1, j = p >> 1, ab = p & 1;
        g_P[(st * 8 + 4 + (sub * 2 + ab)) * 128 + j] = make_float4(c, s, t, r);
    }
    if (idx < 256 * 2) {
        // zero the never-written (s, slot5/7, j=127) entries so no NaNs float around
        int st = idx >> 1, sl = 5 + 2 * (idx & 1);
        g_P[(st * 8 + sl) * 128 + 127] = make_float4(0.f, 0.f, 0.f, 0.f);
    }
    if (idx < n_out) {
        float th = fminf(fmaxf(pout[idx], 0.f), TWO_PI);
        float s, c; sincosf(th, &s, &c);
        g_outP[idx] = make_float2(c, s);
    }
}

// ---------------- degenerate fallback: guarded zero-fill ----------------
__global__ void zero_kernel(float* __restrict__ outf, int n) {
    int idx = blockIdx.x * blockDim.x + threadIdx.x;
    if (idx < n) outf[idx] = 0.f;
}

// ---------------- odd layer: shuffle exchange, smem only at warp edges ------
// Thread j owns rows 4j..4j+3. Internal pair = rows (4j+1,4j+2) -> applyPair.
// Boundary pair = rows (4j+3, 4(j+1)) spans threads j, j+1 (adjacent lanes).
__device__ __forceinline__ void oddLayer(const float4 Pa, const float4 Pb,
                                         u64 re[4], u64 im[4],
                                         ulonglong2* eX, ulonglong2* eY, float* eT,
                                         int j, int w, int l) {
    // boundary precompute (unconditional; j==127 values computed but unused)
    u64 c2 = dup2(Pb.x), s2 = dup2(Pb.y), t2b = dup2(Pb.z), r2b = dup2(Pb.w);
    u64 nr2b = neg2(r2b);
    u64 plr = fma2(c2, re[3], neg2(mul2(s2, im[3])));  // phase row 4j+3
    u64 pli = fma2(c2, im[3], mul2(s2, re[3]));
    u64 Yx = mul2(nr2b, pli);                          // -r * pli
    u64 Yy = mul2(r2b, plr);                           //  r * plr

    // lane exchange: row0 of j+1 flows down; partials of j flow up
    u64 nbRe = __shfl_down_sync(0xffffffffu, re[0], 1);
    u64 nbIm = __shfl_down_sync(0xffffffffu, im[0], 1);
    u64 uYx  = __shfl_up_sync(0xffffffffu, Yx, 1);
    u64 uYy  = __shfl_up_sync(0xffffffffu, Yy, 1);
    float utb = __shfl_up_sync(0xffffffffu, Pb.z, 1);

    // warp-edge traffic via tiny smem
    if (l == 0 && w > 0)  eX[w] = make_ulonglong2(re[0], im[0]);
    if (l == 31 && w < 3) { eY[w] = make_ulonglong2(Yx, Yy); eT[w] = Pb.z; }

    // internal pair while edge data is in flight
    applyPair(Pa, re[1], im[1], re[2], im[2]);

    __syncthreads();

    if (l == 31 && j < 127) { ulonglong2 v = eX[w + 1]; nbRe = v.x; nbIm = v.y; }
    if (l == 0 && w > 0)    { ulonglong2 v = eY[w - 1]; uYx = v.x; uYy = v.y; utb = eT[w - 1]; }

    if (j < 127) {
        re[3] = fma2(t2b, plr, mul2(nr2b, nbIm));   // t*plr - r*bim
        im[3] = fma2(t2b, pli, mul2(r2b, nbRe));    // t*pli + r*bre
    }
    if (j > 0) {
        u64 tn = dup2(utb);
        re[0] = fma2(tn, re[0], uYx);               // t*bre - r*pli(prev)
        im[0] = fma2(tn, im[0], uYy);               // t*bim + r*plr(prev)
    }
}

// ---------------- step-param bundle (coalesced) ----------------
struct SP { float4 q[8]; };
__device__ __forceinline__ SP loadStep(const float4* __restrict__ P, int s, int j) {
    SP r;
#pragma unroll
    for (int k = 0; k < 8; ++k) r.q[k] = P[(s * 8 + k) * 128 + j];
    return r;
}

// ---------------- main mesh kernel ----------------
// grid 256 CTAs (one col-pair each), 128 threads: thread j -> rows 4j..4j+3.
__global__ __launch_bounds__(128, 2) void mesh_kernel(float* __restrict__ outf,
                                                      int mode, int cap) {
    __shared__ ulonglong2 eX[2][4];
    __shared__ ulonglong2 eY[2][4];
    __shared__ float      eT[2][4];

    const int j = threadIdx.x;
    const int w = j >> 5;
    const int l = j & 31;
    const int bx = blockIdx.x;
    const int c0 = bx * 2;
    const int r0 = 4 * j;
    const float4* __restrict__ P = g_P;

    u64 re[4], im[4];
#pragma unroll
    for (int k = 0; k < 4; ++k) {
        int row = r0 + k;
        re[k] = pk2(row == c0 ? 1.f : 0.f, row == c0 + 1 ? 1.f : 0.f);
        im[k] = 0ull;
    }

    SP cur = loadStep(P, 0, j);

    for (int s = 0; s < 256; ++s) {
        const int sn = (s < 255) ? s + 1 : 255;
        SP nxt = loadStep(P, sn, j);   // prefetch next step's params

        // two even sublayers: pairs (2j), (2j+1) thread-internal
        applyPair(cur.q[0], re[0], im[0], re[1], im[1]);
        applyPair(cur.q[1], re[2], im[2], re[3], im[3]);
        applyPair(cur.q[2], re[0], im[0], re[1], im[1]);
        applyPair(cur.q[3], re[2], im[2], re[3], im[3]);

        // two odd sublayers (shuffle exchange; double-buffered edge smem)
        oddLayer(cur.q[4], cur.q[5], re, im, eX[0], eY[0], eT[0], j, w, l);
        oddLayer(cur.q[6], cur.q[7], re, im, eX[1], eY[1], eT[1], j, w, l);

        cur = nxt;
    }

    // output phases (per row), adaptive guarded store
#pragma unroll
    for (int k = 0; k < 4; ++k) {
        int row = r0 + k;
        float2 ph = g_outP[row];
        u64 c2 = dup2(ph.x), s2 = dup2(ph.y);
        u64 nr_ = fma2(c2, re[k], neg2(mul2(s2, im[k])));
        u64 ni_ = fma2(c2, im[k], mul2(s2, re[k]));
        float rl, rh, il, ih;
        up2(nr_, rl, rh);
        up2(ni_, il, ih);

        int ipair = row * 256 + bx;
        if (mode == 0) {
            if (ipair < cap)
                reinterpret_cast<float4*>(outf)[ipair] = make_float4(rl, il, rh, ih);
        } else if (mode == 1) {
            if (ipair < cap)
                reinterpret_cast<float2*>(outf)[ipair] = make_float2(rl, rh);
        } else {
            int base = (row * 512 + c0) * 2;
            if (base + 0 < cap) outf[base + 0] = rl;
            if (base + 1 < cap) outf[base + 1] = il;
            if (base + 2 < cap) outf[base + 2] = rh;
            if (base + 3 < cap) outf[base + 3] = ih;
        }
    }
}

// ---------------- launch ----------------
extern "C" void kernel_launch(void* const* d_in, const int* in_sizes, int n_in,
                              void* d_out, int out_size) {
    float* outf = (float*)d_out;

    if (n_in < 7) {
        int n = out_size > 0 ? out_size : 0;
        if (n > 0) zero_kernel<<<(n + 255) / 256, 256>>>(outf, n);
        return;
    }

    // Resolve input order. Dict/signature order: pe, po, pout, le, ie, lo, io.
    int i_pe = 0, i_po = 1, i_pout = 2, i_le = 3, i_ie = 4, i_lo = 5, i_io = 6;
    if (in_sizes[2] != 512) {
        int ip = -1;
        for (int i = 0; i < 7; ++i) if (in_sizes[i] == 512) ip = i;
        if (ip == 6) {
            i_ie = 0; i_io = 1; i_le = 2; i_lo = 3; i_pe = 4; i_po = 5; i_pout = 6;
        }
    }

    const float* pe   = (const float*)d_in[i_pe];
    const float* po   = (const float*)d_in[i_po];
    const float* pout = (const float*)d_in[i_pout];
    const float* le   = (const float*)d_in[i_le];
    const float* ie   = (const float*)d_in[i_ie];
    const float* lo   = (const float*)d_in[i_lo];
    const float* io   = (const float*)d_in[i_io];

    int n_e = NE, n_o = NO, n_out = 512;
    if (in_sizes[i_pe] < n_e)  n_e = in_sizes[i_pe];
    if (in_sizes[i_le] < n_e)  n_e = in_sizes[i_le];
    if (in_sizes[i_ie] < n_e)  n_e = in_sizes[i_ie];
    if (in_sizes[i_po] < n_o)  n_o = in_sizes[i_po];
    if (in_sizes[i_lo] < n_o)  n_o = in_sizes[i_lo];
    if (in_sizes[i_io] < n_o)  n_o = in_sizes[i_io];
    if (in_sizes[i_pout] < n_out) n_out = in_sizes[i_pout];

    int mode, cap;
    if (out_size >= 524288)      { mode = 0; cap = out_size / 4; if (cap > 131072) cap = 131072; }
    else if (out_size == 262144) { mode = 1; cap = out_size / 2; }
    else                         { mode = 2; cap = out_size; }

    prep_kernel<<<512, 256>>>(pe, po, pout, le, ie, lo, io, n_e, n_o, n_out);
    mesh_kernel<<<256, 128>>>(outf, mode, cap);
}